// round 6
// baseline (speedup 1.0000x reference)
#include <cuda_runtime.h>
#include <math_constants.h>

#define N_MAX 30000
#define M_MAX 10000
#define GYA_MAX 16
#define GYB_MAX 32

// Per-(chunk,point) result slots — written every call, no init needed.
__device__ unsigned long long g_rowA[GYA_MAX * N_MAX];  // (fkey(s)<<32)|argmin_j
__device__ unsigned int      g_colB[GYB_MAX * M_MAX];   // fkey(s)
#define NB_RED 120
__device__ float g_partials[NB_RED];
__device__ int   g_done = 0;   // arrival counter; self-resets each call

// ---------------------------------------------------------------------------
// Packed f32x2 helpers
// ---------------------------------------------------------------------------
__device__ __forceinline__ unsigned long long pack2(float x, float y) {
    unsigned long long r;
    asm("mov.b64 %0, {%1, %2};" : "=l"(r) : "f"(x), "f"(y));
    return r;
}
__device__ __forceinline__ void unpack2(unsigned long long v, float& x, float& y) {
    asm("mov.b64 {%0, %1}, %2;" : "=f"(x), "=f"(y) : "l"(v));
}
__device__ __forceinline__ unsigned long long fma2(unsigned long long a,
                                                   unsigned long long b,
                                                   unsigned long long c) {
    unsigned long long d;
    asm("fma.rn.f32x2 %0, %1, %2, %3;" : "=l"(d) : "l"(a), "l"(b), "l"(c));
    return d;
}

// Sortable-uint encoding for signed floats
__device__ __forceinline__ unsigned int fkey(float f) {
    unsigned int u = __float_as_uint(f);
    return (u & 0x80000000u) ? ~u : (u | 0x80000000u);
}
__device__ __forceinline__ float funkey(unsigned int k) {
    unsigned int u = (k & 0x80000000u) ? (k & 0x7FFFFFFFu) : ~k;
    return __uint_as_float(u);
}

// ---------------------------------------------------------------------------
// Tile layout per point-pair k (points t0,t1, c = 0.5*|t|^2):
//   tile[2k]   = (x0, x1, y0, y1)
//   tile[2k+1] = (z0, z1, c0, c1)
// ---------------------------------------------------------------------------
#define PAIRS   512                 // 1024 points per tile (16 KB smem)
#define TILEPTS (2 * PAIRS)
#define RROWS   4                   // queries per thread
#define TPB     128
#define QPB     (TPB * RROWS)       // 512 queries per block
#define CHUNK   32                  // argmin rescan granularity (pairs)

__device__ __forceinline__ void fill_tile(float4* tile, const float* __restrict__ src,
                                          int beg, int end) {
    const int npair = (end - beg + 1) >> 1;
    for (int k = threadIdx.x; k < npair; k += TPB) {
        const int j0 = beg + 2 * k;
        const int j1 = j0 + 1;
        const float* q0 = src + (size_t)j0 * 3;
        float x0 = q0[0], y0 = q0[1], z0 = q0[2];
        float c0 = 0.5f * fmaf(x0, x0, fmaf(y0, y0, z0 * z0));
        float x1 = 0.f, y1 = 0.f, z1 = 0.f, c1v = CUDART_INF_F;
        if (j1 < end) {
            const float* q1 = src + (size_t)j1 * 3;
            x1 = q1[0]; y1 = q1[1]; z1 = q1[2];
            c1v = 0.5f * fmaf(x1, x1, fmaf(y1, y1, z1 * z1));
        }
        tile[2 * k + 0] = make_float4(x0, x1, y0, y1);
        tile[2 * k + 1] = make_float4(z0, z1, c0, c1v);
    }
}

// ---------------------------------------------------------------------------
// Merged pair kernel.  Flat 1D grid: A items first, then B items.
// A: min+argmin via chunk-record + rescan (main loop = pure fmin chains).
// B: min only.
// ---------------------------------------------------------------------------
__global__ __launch_bounds__(TPB)
void pairs_kernel(const float* __restrict__ P, const float* __restrict__ Ps,
                  int n, int m, int nItemsA, int gyA, int gyB) {
    __shared__ float4 tile[2 * PAIRS];

    const int bid = blockIdx.x;
    const bool isA = (bid < nItemsA);

    const float* qsrc; const float* tsrc;
    int qn, qbase, tbeg, tend, ch;
    if (isA) {
        const int rg = bid / gyA;
        ch = bid - rg * gyA;
        qsrc = P;  qn = n; qbase = rg * QPB;
        tsrc = Ps; tbeg = ch * TILEPTS; tend = min(tbeg + TILEPTS, m);
    } else {
        const int b = bid - nItemsA;
        const int cg = b / gyB;
        ch = b - cg * gyB;
        qsrc = Ps; qn = m; qbase = cg * QPB;
        tsrc = P;  tbeg = ch * TILEPTS; tend = min(tbeg + TILEPTS, n);
    }

    unsigned long long cx[RROWS], cy[RROWS], cz[RROWS];
    float best0[RROWS], best1[RROWS];

    #pragma unroll
    for (int i = 0; i < RROWS; i++) {
        const int row = qbase + i * TPB + threadIdx.x;
        float px = 0.f, py = 0.f, pz = 0.f;
        if (row < qn) {
            px = qsrc[row * 3 + 0];
            py = qsrc[row * 3 + 1];
            pz = qsrc[row * 3 + 2];
        }
        cx[i] = pack2(-px, -px);
        cy[i] = pack2(-py, -py);
        cz[i] = pack2(-pz, -pz);
        best0[i] = CUDART_INF_F;
        best1[i] = CUDART_INF_F;
    }

    fill_tile(tile, tsrc, tbeg, tend);
    __syncthreads();

    const int npair = (tend - tbeg + 1) >> 1;
    const ulonglong2* tl = (const ulonglong2*)tile;

    if (isA) {
        int cst0[RROWS], cst1[RROWS];
        #pragma unroll
        for (int i = 0; i < RROWS; i++) { cst0[i] = 0; cst1[i] = 0; }

        for (int cb = 0; cb < npair; cb += CHUNK) {
            const int kend = min(cb + CHUNK, npair);
            float sn0[RROWS], sn1[RROWS];
            #pragma unroll
            for (int i = 0; i < RROWS; i++) { sn0[i] = best0[i]; sn1[i] = best1[i]; }

            #pragma unroll 4
            for (int k = cb; k < kend; k++) {
                const ulonglong2 t0 = tl[2 * k];       // {x01, y01}
                const ulonglong2 t1 = tl[2 * k + 1];   // {z01, c01}
                #pragma unroll
                for (int i = 0; i < RROWS; i++) {
                    unsigned long long s = fma2(cx[i], t0.x, t1.y);
                    s = fma2(cy[i], t0.y, s);
                    s = fma2(cz[i], t1.x, s);
                    float s0, s1;
                    unpack2(s, s0, s1);
                    best0[i] = fminf(best0[i], s0);
                    best1[i] = fminf(best1[i], s1);
                }
            }
            // a min-chain changes bits only at first attainment of its final
            // value -> last-changed chunk contains the first-occurrence argmin
            #pragma unroll
            for (int i = 0; i < RROWS; i++) {
                if (best0[i] != sn0[i]) cst0[i] = cb;
                if (best1[i] != sn1[i]) cst1[i] = cb;
            }
        }

        // rescan the winning lane's chunk to recover the exact index
        #pragma unroll
        for (int i = 0; i < RROWS; i++) {
            const int row = qbase + i * TPB + threadIdx.x;
            if (row < qn) {
                float v; int kst, lane;
                if (best1[i] < best0[i]) { v = best1[i]; kst = cst1[i]; lane = 1; }
                else                     { v = best0[i]; kst = cst0[i]; lane = 0; }
                const int kend = min(kst + CHUNK, npair);
                int idx = tbeg;
                bool found = false;
                for (int k = kst; k < kend; k++) {
                    const ulonglong2 t0 = tl[2 * k];
                    const ulonglong2 t1 = tl[2 * k + 1];
                    unsigned long long s = fma2(cx[i], t0.x, t1.y);
                    s = fma2(cy[i], t0.y, s);
                    s = fma2(cz[i], t1.x, s);
                    float s0, s1;
                    unpack2(s, s0, s1);
                    const float sl = lane ? s1 : s0;
                    if (!found && sl == v) { idx = tbeg + 2 * k + lane; found = true; }
                }
                g_rowA[ch * N_MAX + row] =
                    ((unsigned long long)fkey(v) << 32) | (unsigned int)idx;
            }
        }
    } else {
        #pragma unroll 4
        for (int k = 0; k < npair; k++) {
            const ulonglong2 t0 = tl[2 * k];
            const ulonglong2 t1 = tl[2 * k + 1];
            #pragma unroll
            for (int i = 0; i < RROWS; i++) {
                unsigned long long s = fma2(cx[i], t0.x, t1.y);
                s = fma2(cy[i], t0.y, s);
                s = fma2(cz[i], t1.x, s);
                float s0, s1;
                unpack2(s, s0, s1);
                best0[i] = fminf(best0[i], s0);
                best1[i] = fminf(best1[i], s1);
            }
        }
        #pragma unroll
        for (int i = 0; i < RROWS; i++) {
            const int col = qbase + i * TPB + threadIdx.x;
            if (col < qn) {
                g_colB[ch * M_MAX + col] = fkey(fminf(best0[i], best1[i]));
            }
        }
    }
}

// ---------------------------------------------------------------------------
// Reduction: per-point min over chunk slots, recover d2 = |pt|^2 + 2*s_min,
// weighted sum; fused final via threadfence + arrival counter (self-resets,
// fixed-order tree sum -> deterministic and graph-replay safe).
// ---------------------------------------------------------------------------
__global__ __launch_bounds__(256)
void reduce_kernel(const float* __restrict__ P, const float* __restrict__ Ps,
                   const float* __restrict__ prob, int n, int m,
                   int gyA, int gyB, float* __restrict__ out) {
    __shared__ float ssum[256];
    __shared__ bool isLast;
    const int stride = gridDim.x * blockDim.x;
    const int tid0 = blockIdx.x * blockDim.x + threadIdx.x;

    float sum = 0.0f;
    for (int i = tid0; i < n; i += stride) {
        unsigned long long b = g_rowA[i];
        for (int c = 1; c < gyA; c++) {
            unsigned long long v = g_rowA[c * N_MAX + i];
            if (v < b) b = v;
        }
        float s = funkey((unsigned int)(b >> 32));
        int j = (int)(unsigned int)(b & 0xFFFFFFFFu);
        float px = P[i * 3 + 0], py = P[i * 3 + 1], pz = P[i * 3 + 2];
        float p2 = fmaf(px, px, fmaf(py, py, pz * pz));
        float d2 = fmaf(2.0f, s, p2);
        sum += sqrtf(fmaxf(d2, 0.0f)) * prob[j];
    }
    for (int i = tid0; i < m; i += stride) {
        unsigned int b = g_colB[i];
        for (int c = 1; c < gyB; c++) {
            unsigned int v = g_colB[c * M_MAX + i];
            if (v < b) b = v;
        }
        float s = funkey(b);
        float qx = Ps[i * 3 + 0], qy = Ps[i * 3 + 1], qz = Ps[i * 3 + 2];
        float q2 = fmaf(qx, qx, fmaf(qy, qy, qz * qz));
        float d2 = fmaf(2.0f, s, q2);
        sum += sqrtf(fmaxf(d2, 0.0f)) * prob[i];
    }

    ssum[threadIdx.x] = sum;
    __syncthreads();
    for (int off = 128; off > 0; off >>= 1) {
        if (threadIdx.x < off) ssum[threadIdx.x] += ssum[threadIdx.x + off];
        __syncthreads();
    }
    if (threadIdx.x == 0) {
        g_partials[blockIdx.x] = ssum[0];
        __threadfence();
        int t = atomicAdd(&g_done, 1);
        isLast = (t == (int)gridDim.x - 1);
    }
    __syncthreads();

    if (isLast) {
        __threadfence();
        volatile float* gp = g_partials;
        float v = (threadIdx.x < (int)gridDim.x) ? gp[threadIdx.x] : 0.0f;
        ssum[threadIdx.x] = v;
        __syncthreads();
        for (int off = 128; off > 0; off >>= 1) {
            if (threadIdx.x < off) ssum[threadIdx.x] += ssum[threadIdx.x + off];
            __syncthreads();
        }
        if (threadIdx.x == 0) {
            out[0] = ssum[0];
            g_done = 0;   // reset for next graph replay
        }
    }
}

// ---------------------------------------------------------------------------
// Launch: 2 kernels total.
// ---------------------------------------------------------------------------
extern "C" void kernel_launch(void* const* d_in, const int* in_sizes, int n_in,
                              void* d_out, int out_size) {
    const float* P    = (const float*)d_in[0];
    const float* Ps   = (const float*)d_in[1];
    const float* prob = (const float*)d_in[2];
    float* out = (float*)d_out;

    const int n = in_sizes[0] / 3;   // 30000
    const int m = in_sizes[1] / 3;   // 10000

    const int gyA = (m + TILEPTS - 1) / TILEPTS;               // 10
    const int rgA = (n + QPB - 1) / QPB;                       // 59
    const int nItemsA = rgA * gyA;                             // 590

    const int gyB = (n + TILEPTS - 1) / TILEPTS;               // 30
    const int cgB = (m + QPB - 1) / QPB;                       // 20
    const int nItemsB = cgB * gyB;                             // 600

    pairs_kernel<<<nItemsA + nItemsB, TPB>>>(P, Ps, n, m, nItemsA, gyA, gyB);
    reduce_kernel<<<NB_RED, 256>>>(P, Ps, prob, n, m, gyA, gyB, out);
}

// round 7
// speedup vs baseline: 1.1714x; 1.1714x over previous
#include <cuda_runtime.h>
#include <math_constants.h>

#define N_MAX 30000
#define M_MAX 10000

// Zero-initialized scratch; zero == sentinel ("worst") under reversed keys.
// reduce_kernel resets entries after consuming them, so every graph replay
// sees clean buffers.  No init kernel needed.
__device__ unsigned long long g_row_best[N_MAX];   // (rkey(s)<<32)|~argmin_j, merged by atomicMax
__device__ unsigned int      g_col_best[M_MAX];    // rkey(s), merged by atomicMax
#define NB_RED 120
__device__ float g_partials[NB_RED];
__device__ int   g_done = 0;   // arrival counter; self-resets each call

// ---------------------------------------------------------------------------
// Packed f32x2 helpers
// ---------------------------------------------------------------------------
__device__ __forceinline__ unsigned long long pack2(float x, float y) {
    unsigned long long r;
    asm("mov.b64 %0, {%1, %2};" : "=l"(r) : "f"(x), "f"(y));
    return r;
}
__device__ __forceinline__ void unpack2(unsigned long long v, float& x, float& y) {
    asm("mov.b64 {%0, %1}, %2;" : "=f"(x), "=f"(y) : "l"(v));
}
__device__ __forceinline__ unsigned long long fma2(unsigned long long a,
                                                   unsigned long long b,
                                                   unsigned long long c) {
    unsigned long long d;
    asm("fma.rn.f32x2 %0, %1, %2, %3;" : "=l"(d) : "l"(a), "l"(b), "l"(c));
    return d;
}

// Sortable encodings.  fkey: float order -> ascending uint.
// rkey = ~fkey: float order -> DESCENDING uint, so atomicMax == min, and 0 is
// the "worse than anything" sentinel (rkey of any finite float is > 0).
__device__ __forceinline__ unsigned int fkey(float f) {
    unsigned int u = __float_as_uint(f);
    return (u & 0x80000000u) ? ~u : (u | 0x80000000u);
}
__device__ __forceinline__ unsigned int rkey(float f) { return ~fkey(f); }
__device__ __forceinline__ float funkey(unsigned int k) {
    unsigned int u = (k & 0x80000000u) ? (k & 0x7FFFFFFFu) : ~k;
    return __uint_as_float(u);
}
__device__ __forceinline__ float r_unkey(unsigned int rk) { return funkey(~rk); }

// ---------------------------------------------------------------------------
// Tile layout per point-pair k (points t0,t1, c = 0.5*|t|^2):
//   tile[2k]   = (x0, x1, y0, y1)
//   tile[2k+1] = (z0, z1, c0, c1)
// ---------------------------------------------------------------------------
#define PAIRS   512                 // 1024 points per tile (16 KB smem)
#define TILEPTS (2 * PAIRS)
#define RROWS   4                   // queries per thread
#define TPB     128
#define QPB     (TPB * RROWS)       // 512 queries per block

__device__ __forceinline__ void fill_tile(float4* tile, const float* __restrict__ src,
                                          int beg, int end) {
    const int npair = (end - beg + 1) >> 1;
    for (int k = threadIdx.x; k < npair; k += TPB) {
        const int j0 = beg + 2 * k;
        const int j1 = j0 + 1;
        const float* q0 = src + (size_t)j0 * 3;
        float x0 = q0[0], y0 = q0[1], z0 = q0[2];
        float c0 = 0.5f * fmaf(x0, x0, fmaf(y0, y0, z0 * z0));
        float x1 = 0.f, y1 = 0.f, z1 = 0.f, c1v = CUDART_INF_F;
        if (j1 < end) {
            const float* q1 = src + (size_t)j1 * 3;
            x1 = q1[0]; y1 = q1[1]; z1 = q1[2];
            c1v = 0.5f * fmaf(x1, x1, fmaf(y1, y1, z1 * z1));
        }
        tile[2 * k + 0] = make_float4(x0, x1, y0, y1);
        tile[2 * k + 1] = make_float4(z0, z1, c0, c1v);
    }
}

// ---------------------------------------------------------------------------
// Merged pair kernel (R5-proven inner loops).  Flat 1D grid: A items, then B.
// ---------------------------------------------------------------------------
__global__ __launch_bounds__(TPB)
void pairs_kernel(const float* __restrict__ P, const float* __restrict__ Ps,
                  int n, int m, int nItemsA, int gyA, int gyB) {
    __shared__ float4 tile[2 * PAIRS];

    const int bid = blockIdx.x;
    const bool isA = (bid < nItemsA);

    const float* qsrc; const float* tsrc;
    int qn, qbase, tbeg, tend;
    if (isA) {
        const int rg = bid / gyA;
        const int ch = bid - rg * gyA;
        qsrc = P;  qn = n; qbase = rg * QPB;
        tsrc = Ps; tbeg = ch * TILEPTS; tend = min(tbeg + TILEPTS, m);
    } else {
        const int b = bid - nItemsA;
        const int cg = b / gyB;
        const int ch = b - cg * gyB;
        qsrc = Ps; qn = m; qbase = cg * QPB;
        tsrc = P;  tbeg = ch * TILEPTS; tend = min(tbeg + TILEPTS, n);
    }

    int rows[RROWS];
    unsigned long long cx[RROWS], cy[RROWS], cz[RROWS];
    float best0[RROWS], best1[RROWS];
    int bidx0[RROWS], bidx1[RROWS];

    #pragma unroll
    for (int i = 0; i < RROWS; i++) {
        const int row = qbase + i * TPB + threadIdx.x;
        rows[i] = row;
        float px = 0.f, py = 0.f, pz = 0.f;
        if (row < qn) {
            px = qsrc[row * 3 + 0];
            py = qsrc[row * 3 + 1];
            pz = qsrc[row * 3 + 2];
        }
        cx[i] = pack2(-px, -px);
        cy[i] = pack2(-py, -py);
        cz[i] = pack2(-pz, -pz);
        best0[i] = CUDART_INF_F;
        best1[i] = CUDART_INF_F;
        bidx0[i] = 0;
        bidx1[i] = 0;
    }

    fill_tile(tile, tsrc, tbeg, tend);
    __syncthreads();

    const int npair = (tend - tbeg + 1) >> 1;
    const ulonglong2* tl = (const ulonglong2*)tile;

    if (isA) {
        // min + argmin (cmp/sel — the fast variant from R5)
        #pragma unroll 4
        for (int k = 0; k < npair; k++) {
            const ulonglong2 t0 = tl[2 * k];       // {x01, y01}
            const ulonglong2 t1 = tl[2 * k + 1];   // {z01, c01}
            const int j0 = tbeg + 2 * k;
            #pragma unroll
            for (int i = 0; i < RROWS; i++) {
                unsigned long long s = fma2(cx[i], t0.x, t1.y);
                s = fma2(cy[i], t0.y, s);
                s = fma2(cz[i], t1.x, s);
                float s0, s1;
                unpack2(s, s0, s1);
                if (s0 < best0[i]) { best0[i] = s0; bidx0[i] = j0; }
                if (s1 < best1[i]) { best1[i] = s1; bidx1[i] = j0 + 1; }
            }
        }
        #pragma unroll
        for (int i = 0; i < RROWS; i++) {
            if (rows[i] < qn) {
                float b = best0[i];
                int bj = bidx0[i];
                if (best1[i] < b) { b = best1[i]; bj = bidx1[i]; }
                // reversed key + complemented index: atomicMax == min over s,
                // ties pick smallest j; zero == sentinel.
                unsigned long long pk =
                    ((unsigned long long)rkey(b) << 32) | (unsigned int)(~bj);
                atomicMax(&g_row_best[rows[i]], pk);
            }
        }
    } else {
        // min only
        #pragma unroll 4
        for (int k = 0; k < npair; k++) {
            const ulonglong2 t0 = tl[2 * k];
            const ulonglong2 t1 = tl[2 * k + 1];
            #pragma unroll
            for (int i = 0; i < RROWS; i++) {
                unsigned long long s = fma2(cx[i], t0.x, t1.y);
                s = fma2(cy[i], t0.y, s);
                s = fma2(cz[i], t1.x, s);
                float s0, s1;
                unpack2(s, s0, s1);
                best0[i] = fminf(best0[i], s0);
                best1[i] = fminf(best1[i], s1);
            }
        }
        #pragma unroll
        for (int i = 0; i < RROWS; i++) {
            if (rows[i] < qn) {
                float b = fminf(best0[i], best1[i]);
                atomicMax(&g_col_best[rows[i]], rkey(b));
            }
        }
    }
}

// ---------------------------------------------------------------------------
// Reduction: recover d2 = |pt|^2 + 2*s_min, weighted sum; resets the consumed
// best-buffers to 0 for the next replay; fused final via threadfence +
// arrival counter (self-resets, fixed-order tree -> deterministic).
// ---------------------------------------------------------------------------
__global__ __launch_bounds__(256)
void reduce_kernel(const float* __restrict__ P, const float* __restrict__ Ps,
                   const float* __restrict__ prob, int n, int m,
                   float* __restrict__ out) {
    __shared__ float ssum[256];
    __shared__ bool isLast;
    const int stride = gridDim.x * blockDim.x;
    const int tid0 = blockIdx.x * blockDim.x + threadIdx.x;

    float sum = 0.0f;
    for (int i = tid0; i < n; i += stride) {
        unsigned long long pk = g_row_best[i];
        g_row_best[i] = 0ull;                      // reset for next replay
        float s = r_unkey((unsigned int)(pk >> 32));
        int j = (int)(~(unsigned int)(pk & 0xFFFFFFFFu));
        float px = P[i * 3 + 0], py = P[i * 3 + 1], pz = P[i * 3 + 2];
        float p2 = fmaf(px, px, fmaf(py, py, pz * pz));
        float d2 = fmaf(2.0f, s, p2);
        sum += sqrtf(fmaxf(d2, 0.0f)) * prob[j];
    }
    for (int i = tid0; i < m; i += stride) {
        unsigned int rk = g_col_best[i];
        g_col_best[i] = 0u;                        // reset for next replay
        float s = r_unkey(rk);
        float qx = Ps[i * 3 + 0], qy = Ps[i * 3 + 1], qz = Ps[i * 3 + 2];
        float q2 = fmaf(qx, qx, fmaf(qy, qy, qz * qz));
        float d2 = fmaf(2.0f, s, q2);
        sum += sqrtf(fmaxf(d2, 0.0f)) * prob[i];
    }

    ssum[threadIdx.x] = sum;
    __syncthreads();
    for (int off = 128; off > 0; off >>= 1) {
        if (threadIdx.x < off) ssum[threadIdx.x] += ssum[threadIdx.x + off];
        __syncthreads();
    }
    if (threadIdx.x == 0) {
        g_partials[blockIdx.x] = ssum[0];
        __threadfence();
        int t = atomicAdd(&g_done, 1);
        isLast = (t == (int)gridDim.x - 1);
    }
    __syncthreads();

    if (isLast) {
        __threadfence();
        volatile float* gp = g_partials;
        float v = (threadIdx.x < (int)gridDim.x) ? gp[threadIdx.x] : 0.0f;
        ssum[threadIdx.x] = v;
        __syncthreads();
        for (int off = 128; off > 0; off >>= 1) {
            if (threadIdx.x < off) ssum[threadIdx.x] += ssum[threadIdx.x + off];
            __syncthreads();
        }
        if (threadIdx.x == 0) {
            out[0] = ssum[0];
            g_done = 0;   // reset for next graph replay
        }
    }
}

// ---------------------------------------------------------------------------
// Launch: 2 kernels total.
// ---------------------------------------------------------------------------
extern "C" void kernel_launch(void* const* d_in, const int* in_sizes, int n_in,
                              void* d_out, int out_size) {
    const float* P    = (const float*)d_in[0];
    const float* Ps   = (const float*)d_in[1];
    const float* prob = (const float*)d_in[2];
    float* out = (float*)d_out;

    const int n = in_sizes[0] / 3;   // 30000
    const int m = in_sizes[1] / 3;   // 10000

    const int gyA = (m + TILEPTS - 1) / TILEPTS;               // 10
    const int rgA = (n + QPB - 1) / QPB;                       // 59
    const int nItemsA = rgA * gyA;                             // 590

    const int gyB = (n + TILEPTS - 1) / TILEPTS;               // 30
    const int cgB = (m + QPB - 1) / QPB;                       // 20
    const int nItemsB = cgB * gyB;                             // 600

    pairs_kernel<<<nItemsA + nItemsB, TPB>>>(P, Ps, n, m, nItemsA, gyA, gyB);
    reduce_kernel<<<NB_RED, 256>>>(P, Ps, prob, n, m, out);
}